// round 1
// baseline (speedup 1.0000x reference)
#include <cuda_runtime.h>
#include <math_constants.h>
#include <cstdint>

#define Bq  4
#define Np  8192
#define Mq  2048
#define DP  128
#define DM  256
#define KNN 16
#define BM  8192            // Bq*Mq
#define RES_ELEMS (BM*DP)   // 1048576

// ---------------- scratch (static device allocations are allowed) ----------
__device__ int   g_knn[BM*KNN];
__device__ float g_q  [BM*DM];
__device__ float g_x  [BM*KNN*DM];
__device__ float g_k  [BM*KNN*DM];
__device__ float g_v  [BM*KNN*DM];
__device__ float g_pos[BM*KNN*DM];

// ---------------- KNN: warp per query, register top-16 + shfl merge --------
__global__ void knn_kernel(const float* __restrict__ xyz,
                           const float* __restrict__ query) {
    int wip  = threadIdx.x >> 5;
    int lane = threadIdx.x & 31;
    int qi   = blockIdx.x * 8 + wip;          // 0..8191
    int b    = qi >> 11;                      // /2048
    const float* qp = query + (size_t)qi * 131;
    float qx = qp[0], qy = qp[1], qz = qp[2];
    float q2 = qx*qx + qy*qy + qz*qz;
    const float* xb = xyz + (size_t)b * Np * 3;

    float bd[16];
    int   bi[16];
#pragma unroll
    for (int i = 0; i < 16; i++) { bd[i] = CUDART_INF_F; bi[i] = 0x7fffffff; }
    float cm = CUDART_INF_F; int cmp_ = 0;

    for (int n = lane; n < Np; n += 32) {
        float x = xb[3*n], y = xb[3*n+1], z = xb[3*n+2];
        float d = q2 + (x*x + y*y + z*z) - 2.0f*(qx*x + qy*y + qz*z);
        if (d < cm) {
#pragma unroll
            for (int i = 0; i < 16; i++) if (i == cmp_) { bd[i] = d; bi[i] = n; }
            cm = -CUDART_INF_F;
#pragma unroll
            for (int i = 0; i < 16; i++) if (bd[i] > cm) { cm = bd[i]; cmp_ = i; }
        }
    }

    // 16 rounds of warp-wide argmin (ascending distance, low-index tiebreak)
    for (int r = 0; r < 16; r++) {
        float md = CUDART_INF_F; int mi = 0x7fffffff;
#pragma unroll
        for (int i = 0; i < 16; i++) {
            float d = bd[i]; int id = bi[i];
            if (d < md || (d == md && id < mi)) { md = d; mi = id; }
        }
#pragma unroll
        for (int off = 16; off > 0; off >>= 1) {
            float od = __shfl_down_sync(0xffffffffu, md, off);
            int   oi = __shfl_down_sync(0xffffffffu, mi, off);
            if (od < md || (od == md && oi < mi)) { md = od; mi = oi; }
        }
        int w = __shfl_sync(0xffffffffu, mi, 0);
        if (lane == 0) g_knn[qi*16 + r] = w;
#pragma unroll
        for (int i = 0; i < 16; i++) if (bi[i] == w) bd[i] = CUDART_INF_F;
    }
}

// ---------------- q = query_f @ wq (no bias): 16 rows/block, 128 thr -------
__global__ void qproj_kernel(const float* __restrict__ query,
                             const float* __restrict__ wq) {
    __shared__ float sin_[16][DP];
    int r0 = blockIdx.x * 16;
    for (int t = threadIdx.x; t < 16*DP; t += 128) {
        int r = t >> 7, k = t & 127;
        sin_[r][k] = query[(size_t)(r0 + r)*131 + 3 + k];
    }
    __syncthreads();
    int c0 = threadIdx.x, c1 = threadIdx.x + 128;
    float a0[16], a1[16];
#pragma unroll
    for (int r = 0; r < 16; r++) { a0[r] = 0.f; a1[r] = 0.f; }
#pragma unroll 4
    for (int k = 0; k < DP; k++) {
        float w0 = wq[k*DM + c0];
        float w1 = wq[k*DM + c1];
#pragma unroll
        for (int r = 0; r < 16; r++) {
            float s = sin_[r][k];
            a0[r] = fmaf(s, w0, a0[r]);
            a1[r] = fmaf(s, w1, a1[r]);
        }
    }
#pragma unroll
    for (int r = 0; r < 16; r++) {
        g_q[(size_t)(r0+r)*DM + c0] = a0[r];
        g_q[(size_t)(r0+r)*DM + c1] = a1[r];
    }
}

// ---------------- x = gather(features) @ fc1 + b : block per query ---------
__global__ void fc1_kernel(const float* __restrict__ feat,
                           const float* __restrict__ w,
                           const float* __restrict__ bias) {
    __shared__ float sin_[16][DP];
    __shared__ int   sidx[16];
    int bm = blockIdx.x;
    int b  = bm >> 11;
    if (threadIdx.x < 16) sidx[threadIdx.x] = g_knn[bm*16 + threadIdx.x];
    __syncthreads();
    for (int t = threadIdx.x; t < 16*DP; t += 128) {
        int r = t >> 7, k = t & 127;
        sin_[r][k] = feat[((size_t)b*Np + sidx[r])*DP + k];
    }
    __syncthreads();
    int c0 = threadIdx.x, c1 = threadIdx.x + 128;
    float b0 = bias[c0], b1 = bias[c1];
    float a0[16], a1[16];
#pragma unroll
    for (int r = 0; r < 16; r++) { a0[r] = b0; a1[r] = b1; }
#pragma unroll 4
    for (int k = 0; k < DP; k++) {
        float w0 = w[k*DM + c0];
        float w1 = w[k*DM + c1];
#pragma unroll
        for (int r = 0; r < 16; r++) {
            float s = sin_[r][k];
            a0[r] = fmaf(s, w0, a0[r]);
            a1[r] = fmaf(s, w1, a1[r]);
        }
    }
    float* xo = g_x + (size_t)bm*16*DM;
#pragma unroll
    for (int r = 0; r < 16; r++) {
        xo[r*DM + c0] = a0[r];
        xo[r*DM + c1] = a1[r];
    }
}

// ---------------- k = x@wk, v = x@wv : block per query, 256 thr ------------
__global__ void kv_kernel(const float* __restrict__ wk,
                          const float* __restrict__ wv) {
    __shared__ float sin_[16][DM];
    int bm = blockIdx.x;
    const float* xr = g_x + (size_t)bm*16*DM;
    for (int t = threadIdx.x; t < 16*DM; t += 256) ((float*)sin_)[t] = xr[t];
    __syncthreads();
    int c = threadIdx.x;
    float ak[16], av[16];
#pragma unroll
    for (int r = 0; r < 16; r++) { ak[r] = 0.f; av[r] = 0.f; }
#pragma unroll 4
    for (int k = 0; k < DM; k++) {
        float wkv = wk[k*DM + c];
        float wvv = wv[k*DM + c];
#pragma unroll
        for (int r = 0; r < 16; r++) {
            float s = sin_[r][k];
            ak[r] = fmaf(s, wkv, ak[r]);
            av[r] = fmaf(s, wvv, av[r]);
        }
    }
    float* ko = g_k + (size_t)bm*16*DM;
    float* vo = g_v + (size_t)bm*16*DM;
#pragma unroll
    for (int r = 0; r < 16; r++) {
        ko[r*DM + c] = ak[r];
        vo[r*DM + c] = av[r];
    }
}

// ---------------- pos_enc = relu(delta@d1+b)@d2+b : block per query --------
__global__ void pos_kernel(const float* __restrict__ xyz,
                           const float* __restrict__ query,
                           const float* __restrict__ d1w, const float* __restrict__ d1b,
                           const float* __restrict__ d2w, const float* __restrict__ d2b) {
    __shared__ float sh_[16][DM];
    __shared__ float sdel[16][3];
    int bm = blockIdx.x, b = bm >> 11;
    if (threadIdx.x < 16) {
        int idx = g_knn[bm*16 + threadIdx.x];
        const float* qp = query + (size_t)bm*131;
        const float* xp = xyz + ((size_t)b*Np + idx)*3;
        sdel[threadIdx.x][0] = qp[0] - xp[0];
        sdel[threadIdx.x][1] = qp[1] - xp[1];
        sdel[threadIdx.x][2] = qp[2] - xp[2];
    }
    __syncthreads();
    int c0 = threadIdx.x, c1 = threadIdx.x + 128;
    {
        float w00 = d1w[c0],      w01 = d1w[c1];
        float w10 = d1w[DM+c0],   w11 = d1w[DM+c1];
        float w20 = d1w[2*DM+c0], w21 = d1w[2*DM+c1];
        float bb0 = d1b[c0],      bb1 = d1b[c1];
#pragma unroll
        for (int r = 0; r < 16; r++) {
            float dx = sdel[r][0], dy = sdel[r][1], dz = sdel[r][2];
            sh_[r][c0] = fmaxf(fmaf(dz, w20, fmaf(dy, w10, fmaf(dx, w00, bb0))), 0.f);
            sh_[r][c1] = fmaxf(fmaf(dz, w21, fmaf(dy, w11, fmaf(dx, w01, bb1))), 0.f);
        }
    }
    __syncthreads();
    float a0[16], a1[16];
    float b0 = d2b[c0], b1 = d2b[c1];
#pragma unroll
    for (int r = 0; r < 16; r++) { a0[r] = b0; a1[r] = b1; }
#pragma unroll 4
    for (int k = 0; k < DM; k++) {
        float w0 = d2w[k*DM + c0];
        float w1 = d2w[k*DM + c1];
#pragma unroll
        for (int r = 0; r < 16; r++) {
            float s = sh_[r][k];
            a0[r] = fmaf(s, w0, a0[r]);
            a1[r] = fmaf(s, w1, a1[r]);
        }
    }
    float* po = g_pos + (size_t)bm*16*DM;
#pragma unroll
    for (int r = 0; r < 16; r++) {
        po[r*DM + c0] = a0[r];
        po[r*DM + c1] = a1[r];
    }
}

// ------- attn_pre = relu((q-k+pos)@g1+b)@g2+b  -> d_out attn region --------
__global__ void attnpre_kernel(const float* __restrict__ g1w, const float* __restrict__ g1b,
                               const float* __restrict__ g2w, const float* __restrict__ g2b,
                               float* __restrict__ out) {
    __shared__ float sa[16][DM];
    __shared__ float sh_[16][DM];
    int bm = blockIdx.x;
    int c0 = threadIdx.x, c1 = c0 + 128;
    float q0 = g_q[(size_t)bm*DM + c0];
    float q1 = g_q[(size_t)bm*DM + c1];
    const float* kr = g_k   + (size_t)bm*16*DM;
    const float* pr = g_pos + (size_t)bm*16*DM;
#pragma unroll
    for (int r = 0; r < 16; r++) {
        sa[r][c0] = q0 - kr[r*DM + c0] + pr[r*DM + c0];
        sa[r][c1] = q1 - kr[r*DM + c1] + pr[r*DM + c1];
    }
    __syncthreads();
    float a0[16], a1[16];
    float b0 = g1b[c0], b1 = g1b[c1];
#pragma unroll
    for (int r = 0; r < 16; r++) { a0[r] = b0; a1[r] = b1; }
#pragma unroll 4
    for (int k = 0; k < DM; k++) {
        float w0 = g1w[k*DM + c0];
        float w1 = g1w[k*DM + c1];
#pragma unroll
        for (int r = 0; r < 16; r++) {
            float s = sa[r][k];
            a0[r] = fmaf(s, w0, a0[r]);
            a1[r] = fmaf(s, w1, a1[r]);
        }
    }
#pragma unroll
    for (int r = 0; r < 16; r++) {
        sh_[r][c0] = fmaxf(a0[r], 0.f);
        sh_[r][c1] = fmaxf(a1[r], 0.f);
    }
    __syncthreads();
    b0 = g2b[c0]; b1 = g2b[c1];
#pragma unroll
    for (int r = 0; r < 16; r++) { a0[r] = b0; a1[r] = b1; }
#pragma unroll 4
    for (int k = 0; k < DM; k++) {
        float w0 = g2w[k*DM + c0];
        float w1 = g2w[k*DM + c1];
#pragma unroll
        for (int r = 0; r < 16; r++) {
            float s = sh_[r][k];
            a0[r] = fmaf(s, w0, a0[r]);
            a1[r] = fmaf(s, w1, a1[r]);
        }
    }
    float* ao = out + RES_ELEMS + (size_t)bm*16*DM;
#pragma unroll
    for (int r = 0; r < 16; r++) {
        ao[r*DM + c0] = a0[r];
        ao[r*DM + c1] = a1[r];
    }
}

// ------- softmax (in-place in d_out) + weighted sum + fc2 + residual -------
__global__ void final_kernel(const float* __restrict__ fc2w, const float* __restrict__ fc2b,
                             const float* __restrict__ query, float* __restrict__ out) {
    __shared__ float sres[DM];
    int bm = blockIdx.x, c = threadIdx.x;
    float* attn = out + RES_ELEMS + (size_t)bm*16*DM;
    float ap[16];
#pragma unroll
    for (int j = 0; j < 16; j++) ap[j] = attn[j*DM + c] * 0.0625f;  // / sqrt(256)
    float mx = ap[0];
#pragma unroll
    for (int j = 1; j < 16; j++) mx = fmaxf(mx, ap[j]);
    float s = 0.f;
#pragma unroll
    for (int j = 0; j < 16; j++) { ap[j] = expf(ap[j] - mx); s += ap[j]; }
    float inv = 1.0f / s;
    const float* vr = g_v   + (size_t)bm*16*DM;
    const float* pr = g_pos + (size_t)bm*16*DM;
    float resc = 0.f;
#pragma unroll
    for (int j = 0; j < 16; j++) {
        float a = ap[j] * inv;
        attn[j*DM + c] = a;
        resc = fmaf(a, vr[j*DM + c] + pr[j*DM + c], resc);
    }
    sres[c] = resc;
    __syncthreads();
    if (c < DP) {
        float acc = fc2b[c];
#pragma unroll 4
        for (int k = 0; k < DM; k++) acc = fmaf(sres[k], fc2w[k*DP + c], acc);
        acc += query[(size_t)bm*131 + 3 + c];
        out[(size_t)bm*DP + c] = acc;
    }
}

// ---------------------------------------------------------------------------
extern "C" void kernel_launch(void* const* d_in, const int* in_sizes, int n_in,
                              void* d_out, int out_size) {
    const float* xyz   = (const float*)d_in[0];
    const float* feat  = (const float*)d_in[1];
    const float* query = (const float*)d_in[2];
    const float* fc1w  = (const float*)d_in[3];
    const float* fc1b  = (const float*)d_in[4];
    const float* fc2w  = (const float*)d_in[5];
    const float* fc2b  = (const float*)d_in[6];
    const float* d1w   = (const float*)d_in[7];
    const float* d1b   = (const float*)d_in[8];
    const float* d2w   = (const float*)d_in[9];
    const float* d2b   = (const float*)d_in[10];
    const float* g1w   = (const float*)d_in[11];
    const float* g1b   = (const float*)d_in[12];
    const float* g2w   = (const float*)d_in[13];
    const float* g2b   = (const float*)d_in[14];
    const float* wq    = (const float*)d_in[15];
    const float* wk    = (const float*)d_in[16];
    const float* wv    = (const float*)d_in[17];
    float* out = (float*)d_out;

    knn_kernel   <<<BM/8, 256>>>(xyz, query);
    qproj_kernel <<<BM/16, 128>>>(query, wq);
    fc1_kernel   <<<BM, 128>>>(feat, fc1w, fc1b);
    kv_kernel    <<<BM, 256>>>(wk, wv);
    pos_kernel   <<<BM, 128>>>(xyz, query, d1w, d1b, d2w, d2b);
    attnpre_kernel<<<BM, 128>>>(g1w, g1b, g2w, g2b, out);
    final_kernel <<<BM, 256>>>(fc2w, fc2b, query, out);
}

// round 3
// speedup vs baseline: 2.2193x; 2.2193x over previous
#include <cuda_runtime.h>
#include <math_constants.h>
#include <cstdint>

#define Bq  4
#define Np  8192
#define Mq  2048
#define DP  128
#define DM  256
#define KNN 16
#define BM  8192            // Bq*Mq
#define RES_ELEMS (BM*DP)   // 1048576

typedef unsigned long long ull;

// ---------------- packed f32x2 helpers -------------------------------------
__device__ __forceinline__ ull pack2(float lo, float hi) {
    ull r; asm("mov.b64 %0, {%1, %2};" : "=l"(r) : "f"(lo), "f"(hi)); return r;
}
__device__ __forceinline__ ull bcast2(float v) { return pack2(v, v); }
__device__ __forceinline__ void fma2(ull& d, ull a, ull b) {
    asm("fma.rn.f32x2 %0, %1, %2, %3;" : "=l"(d) : "l"(a), "l"(b), "l"(d));
}
__device__ __forceinline__ float2 unpack2(ull v) {
    float2 r; asm("mov.b64 {%0, %1}, %2;" : "=f"(r.x), "=f"(r.y) : "l"(v)); return r;
}

// ---------------- scratch --------------------------------------------------
__device__ int   g_knn[BM*KNN];
__device__ float g_q  [BM*DM];
__device__ float g_k  [BM*KNN*DM];
__device__ float g_v  [BM*KNN*DM];
__device__ float g_pos[BM*KNN*DM];

// ---------------- KNN: warp per query, register top-16 + shfl merge --------
__global__ void knn_kernel(const float* __restrict__ xyz,
                           const float* __restrict__ query) {
    int wip  = threadIdx.x >> 5;
    int lane = threadIdx.x & 31;
    int qi   = blockIdx.x * 8 + wip;
    int b    = qi >> 11;
    const float* qp = query + (size_t)qi * 131;
    float qx = qp[0], qy = qp[1], qz = qp[2];
    float q2 = qx*qx + qy*qy + qz*qz;
    const float* xb = xyz + (size_t)b * Np * 3;

    float bd[16];
    int   bi[16];
#pragma unroll
    for (int i = 0; i < 16; i++) { bd[i] = CUDART_INF_F; bi[i] = 0x7fffffff; }
    float cm = CUDART_INF_F; int cmp_ = 0;

    for (int n = lane; n < Np; n += 32) {
        float x = xb[3*n], y = xb[3*n+1], z = xb[3*n+2];
        float d = q2 + (x*x + y*y + z*z) - 2.0f*(qx*x + qy*y + qz*z);
        if (d < cm) {
#pragma unroll
            for (int i = 0; i < 16; i++) if (i == cmp_) { bd[i] = d; bi[i] = n; }
            cm = -CUDART_INF_F;
#pragma unroll
            for (int i = 0; i < 16; i++) if (bd[i] > cm) { cm = bd[i]; cmp_ = i; }
        }
    }

    for (int r = 0; r < 16; r++) {
        float md = CUDART_INF_F; int mi = 0x7fffffff;
#pragma unroll
        for (int i = 0; i < 16; i++) {
            float d = bd[i]; int id = bi[i];
            if (d < md || (d == md && id < mi)) { md = d; mi = id; }
        }
#pragma unroll
        for (int off = 16; off > 0; off >>= 1) {
            float od = __shfl_down_sync(0xffffffffu, md, off);
            int   oi = __shfl_down_sync(0xffffffffu, mi, off);
            if (od < md || (od == md && oi < mi)) { md = od; mi = oi; }
        }
        int w = __shfl_sync(0xffffffffu, mi, 0);
        if (lane == 0) g_knn[qi*16 + r] = w;
#pragma unroll
        for (int i = 0; i < 16; i++) if (bi[i] == w) bd[i] = CUDART_INF_F;
    }
}

// ---------------- q = query_f @ wq : 16 queries/block, 128 thr, FFMA2 ------
__global__ __launch_bounds__(128) void qproj_kernel(const float* __restrict__ query,
                                                    const float* __restrict__ wq) {
    __shared__ float sT[DP][18];
    int r0 = blockIdx.x * 16, tid = threadIdx.x;
    for (int t = tid; t < 16*DP; t += 128) {
        int r = t >> 7, k = t & 127;
        sT[k][r] = query[(size_t)(r0 + r)*131 + 3 + k];
    }
    __syncthreads();
    int c0 = 2*tid;
    ull a0[8], a1[8];
#pragma unroll
    for (int p = 0; p < 8; p++) { a0[p] = 0ull; a1[p] = 0ull; }
#pragma unroll 2
    for (int k = 0; k < DP; k++) {
        float2 w = *(const float2*)&wq[k*DM + c0];
        ull w0 = bcast2(w.x), w1 = bcast2(w.y);
#pragma unroll
        for (int p = 0; p < 8; p++) {
            ull s = *(const ull*)&sT[k][2*p];
            fma2(a0[p], s, w0);
            fma2(a1[p], s, w1);
        }
    }
#pragma unroll
    for (int p = 0; p < 8; p++) {
        float2 v0 = unpack2(a0[p]), v1 = unpack2(a1[p]);
        g_q[(size_t)(r0+2*p  )*DM + c0  ] = v0.x;
        g_q[(size_t)(r0+2*p+1)*DM + c0  ] = v0.y;
        g_q[(size_t)(r0+2*p  )*DM + c0+1] = v1.x;
        g_q[(size_t)(r0+2*p+1)*DM + c0+1] = v1.y;
    }
}

// -------- fused: x = gather(feat)@fc1+b ; k = x@wk ; v = x@wv --------------
__global__ __launch_bounds__(128) void fc1kv_kernel(const float* __restrict__ feat,
                                                    const float* __restrict__ fc1w,
                                                    const float* __restrict__ fc1b,
                                                    const float* __restrict__ wk,
                                                    const float* __restrict__ wv) {
    __shared__ float sT[DP][18];
    __shared__ float xT[DM][18];
    __shared__ int   sidx[16];
    int bm = blockIdx.x, b = bm >> 11, tid = threadIdx.x;
    if (tid < 16) sidx[tid] = g_knn[bm*16 + tid];
    __syncthreads();
    for (int t = tid; t < 16*DP; t += 128) {
        int r = t >> 7, k = t & 127;
        sT[k][r] = feat[((size_t)b*Np + sidx[r])*DP + k];
    }
    __syncthreads();

    int c0 = 2*tid;
    // GEMM1: x (16 x 256) over K=128
    {
        float2 bb = *(const float2*)&fc1b[c0];
        ull a0[8], a1[8];
#pragma unroll
        for (int p = 0; p < 8; p++) { a0[p] = bcast2(bb.x); a1[p] = bcast2(bb.y); }
#pragma unroll 2
        for (int k = 0; k < DP; k++) {
            float2 w = *(const float2*)&fc1w[k*DM + c0];
            ull w0 = bcast2(w.x), w1 = bcast2(w.y);
#pragma unroll
            for (int p = 0; p < 8; p++) {
                ull s = *(const ull*)&sT[k][2*p];
                fma2(a0[p], s, w0);
                fma2(a1[p], s, w1);
            }
        }
#pragma unroll
        for (int p = 0; p < 8; p++) {
            float2 v0 = unpack2(a0[p]), v1 = unpack2(a1[p]);
            xT[c0  ][2*p] = v0.x;  xT[c0  ][2*p+1] = v0.y;
            xT[c0+1][2*p] = v1.x;  xT[c0+1][2*p+1] = v1.y;
        }
    }
    __syncthreads();

    // GEMM2: k = x@wk, v = x@wv over K=256
    ull k0[8], k1[8], v0a[8], v1a[8];
#pragma unroll
    for (int p = 0; p < 8; p++) { k0[p]=0ull; k1[p]=0ull; v0a[p]=0ull; v1a[p]=0ull; }
#pragma unroll 2
    for (int k = 0; k < DM; k++) {
        float2 wk2 = *(const float2*)&wk[k*DM + c0];
        float2 wv2 = *(const float2*)&wv[k*DM + c0];
        ull wk0 = bcast2(wk2.x), wk1 = bcast2(wk2.y);
        ull wv0 = bcast2(wv2.x), wv1 = bcast2(wv2.y);
#pragma unroll
        for (int p = 0; p < 8; p++) {
            ull s = *(const ull*)&xT[k][2*p];
            fma2(k0[p],  s, wk0);
            fma2(k1[p],  s, wk1);
            fma2(v0a[p], s, wv0);
            fma2(v1a[p], s, wv1);
        }
    }
    float* ko = g_k + (size_t)bm*16*DM;
    float* vo = g_v + (size_t)bm*16*DM;
#pragma unroll
    for (int p = 0; p < 8; p++) {
        float2 f;
        f = unpack2(k0[p]);  ko[(2*p)*DM + c0  ] = f.x; ko[(2*p+1)*DM + c0  ] = f.y;
        f = unpack2(k1[p]);  ko[(2*p)*DM + c0+1] = f.x; ko[(2*p+1)*DM + c0+1] = f.y;
        f = unpack2(v0a[p]); vo[(2*p)*DM + c0  ] = f.x; vo[(2*p+1)*DM + c0  ] = f.y;
        f = unpack2(v1a[p]); vo[(2*p)*DM + c0+1] = f.x; vo[(2*p+1)*DM + c0+1] = f.y;
    }
}

// ---------------- pos_enc = relu(delta@d1+b)@d2+b --------------------------
__global__ __launch_bounds__(128) void pos_kernel(const float* __restrict__ xyz,
                                                  const float* __restrict__ query,
                                                  const float* __restrict__ d1w, const float* __restrict__ d1b,
                                                  const float* __restrict__ d2w, const float* __restrict__ d2b) {
    __shared__ float hT[DM][18];
    __shared__ float sdel[16][4];
    int bm = blockIdx.x, b = bm >> 11, tid = threadIdx.x;
    if (tid < 16) {
        int idx = g_knn[bm*16 + tid];
        const float* qp = query + (size_t)bm*131;
        const float* xp = xyz + ((size_t)b*Np + idx)*3;
        sdel[tid][0] = qp[0] - xp[0];
        sdel[tid][1] = qp[1] - xp[1];
        sdel[tid][2] = qp[2] - xp[2];
    }
    __syncthreads();
    int c0 = 2*tid;
    {
        float w00 = d1w[c0],      w01 = d1w[c0+1];
        float w10 = d1w[DM+c0],   w11 = d1w[DM+c0+1];
        float w20 = d1w[2*DM+c0], w21 = d1w[2*DM+c0+1];
        float bb0 = d1b[c0],      bb1 = d1b[c0+1];
#pragma unroll
        for (int r = 0; r < 16; r++) {
            float dx = sdel[r][0], dy = sdel[r][1], dz = sdel[r][2];
            hT[c0  ][r] = fmaxf(fmaf(dz, w20, fmaf(dy, w10, fmaf(dx, w00, bb0))), 0.f);
            hT[c0+1][r] = fmaxf(fmaf(dz, w21, fmaf(dy, w11, fmaf(dx, w01, bb1))), 0.f);
        }
    }
    __syncthreads();
    float2 bb = *(const float2*)&d2b[c0];
    ull a0[8], a1[8];
#pragma unroll
    for (int p = 0; p < 8; p++) { a0[p] = bcast2(bb.x); a1[p] = bcast2(bb.y); }
#pragma unroll 2
    for (int k = 0; k < DM; k++) {
        float2 w = *(const float2*)&d2w[k*DM + c0];
        ull w0 = bcast2(w.x), w1 = bcast2(w.y);
#pragma unroll
        for (int p = 0; p < 8; p++) {
            ull s = *(const ull*)&hT[k][2*p];
            fma2(a0[p], s, w0);
            fma2(a1[p], s, w1);
        }
    }
    float* po = g_pos + (size_t)bm*16*DM;
#pragma unroll
    for (int p = 0; p < 8; p++) {
        float2 f;
        f = unpack2(a0[p]); po[(2*p)*DM + c0  ] = f.x; po[(2*p+1)*DM + c0  ] = f.y;
        f = unpack2(a1[p]); po[(2*p)*DM + c0+1] = f.x; po[(2*p+1)*DM + c0+1] = f.y;
    }
}

// ------- attn_pre = relu((q-k+pos)@g1+b)@g2+b  -> d_out attn region --------
__global__ __launch_bounds__(128) void attnpre_kernel(const float* __restrict__ g1w, const float* __restrict__ g1b,
                                                      const float* __restrict__ g2w, const float* __restrict__ g2b,
                                                      float* __restrict__ out) {
    __shared__ float aT[DM][18];
    int bm = blockIdx.x, tid = threadIdx.x;
    int c0 = 2*tid;
    const float* kr = g_k   + (size_t)bm*16*DM;
    const float* pr = g_pos + (size_t)bm*16*DM;
    float2 qv = *(const float2*)&g_q[(size_t)bm*DM + c0];
#pragma unroll
    for (int r = 0; r < 16; r++) {
        float2 kk = *(const float2*)&kr[r*DM + c0];
        float2 pp = *(const float2*)&pr[r*DM + c0];
        aT[c0  ][r] = qv.x - kk.x + pp.x;
        aT[c0+1][r] = qv.y - kk.y + pp.y;
    }
    __syncthreads();

    ull a0[8], a1[8];
    {
        float2 bb = *(const float2*)&g1b[c0];
#pragma unroll
        for (int p = 0; p < 8; p++) { a0[p] = bcast2(bb.x); a1[p] = bcast2(bb.y); }
    }
#pragma unroll 2
    for (int k = 0; k < DM; k++) {
        float2 w = *(const float2*)&g1w[k*DM + c0];
        ull w0 = bcast2(w.x), w1 = bcast2(w.y);
#pragma unroll
        for (int p = 0; p < 8; p++) {
            ull s = *(const ull*)&aT[k][2*p];
            fma2(a0[p], s, w0);
            fma2(a1[p], s, w1);
        }
    }
    __syncthreads();   // all reads of aT done before overwrite
#pragma unroll
    for (int p = 0; p < 8; p++) {
        float2 f0 = unpack2(a0[p]), f1 = unpack2(a1[p]);
        aT[c0  ][2*p] = fmaxf(f0.x, 0.f);  aT[c0  ][2*p+1] = fmaxf(f0.y, 0.f);
        aT[c0+1][2*p] = fmaxf(f1.x, 0.f);  aT[c0+1][2*p+1] = fmaxf(f1.y, 0.f);
    }
    __syncthreads();
    {
        float2 bb = *(const float2*)&g2b[c0];
#pragma unroll
        for (int p = 0; p < 8; p++) { a0[p] = bcast2(bb.x); a1[p] = bcast2(bb.y); }
    }
#pragma unroll 2
    for (int k = 0; k < DM; k++) {
        float2 w = *(const float2*)&g2w[k*DM + c0];
        ull w0 = bcast2(w.x), w1 = bcast2(w.y);
#pragma unroll
        for (int p = 0; p < 8; p++) {
            ull s = *(const ull*)&aT[k][2*p];
            fma2(a0[p], s, w0);
            fma2(a1[p], s, w1);
        }
    }
    float* ao = out + RES_ELEMS + (size_t)bm*16*DM;
#pragma unroll
    for (int p = 0; p < 8; p++) {
        float2 f;
        f = unpack2(a0[p]); ao[(2*p)*DM + c0  ] = f.x; ao[(2*p+1)*DM + c0  ] = f.y;
        f = unpack2(a1[p]); ao[(2*p)*DM + c0+1] = f.x; ao[(2*p+1)*DM + c0+1] = f.y;
    }
}

// ------- softmax (in-place in d_out) + weighted sum + fc2 + residual -------
__global__ void final_kernel(const float* __restrict__ fc2w, const float* __restrict__ fc2b,
                             const float* __restrict__ query, float* __restrict__ out) {
    __shared__ float sres[DM];
    int bm = blockIdx.x, c = threadIdx.x;
    float* attn = out + RES_ELEMS + (size_t)bm*16*DM;
    float ap[16];
#pragma unroll
    for (int j = 0; j < 16; j++) ap[j] = attn[j*DM + c] * 0.0625f;
    float mx = ap[0];
#pragma unroll
    for (int j = 1; j < 16; j++) mx = fmaxf(mx, ap[j]);
    float s = 0.f;
#pragma unroll
    for (int j = 0; j < 16; j++) { ap[j] = expf(ap[j] - mx); s += ap[j]; }
    float inv = 1.0f / s;
    const float* vr = g_v   + (size_t)bm*16*DM;
    const float* pr = g_pos + (size_t)bm*16*DM;
    float resc = 0.f;
#pragma unroll
    for (int j = 0; j < 16; j++) {
        float a = ap[j] * inv;
        attn[j*DM + c] = a;
        resc = fmaf(a, vr[j*DM + c] + pr[j*DM + c], resc);
    }
    sres[c] = resc;
    __syncthreads();
    if (c < DP) {
        float acc = fc2b[c];
#pragma unroll 4
        for (int k = 0; k < DM; k++) acc = fmaf(sres[k], fc2w[k*DP + c], acc);
        acc += query[(size_t)bm*131 + 3 + c];
        out[(size_t)bm*DP + c] = acc;
    }
}

// ---------------------------------------------------------------------------
extern "C" void kernel_launch(void* const* d_in, const int* in_sizes, int n_in,
                              void* d_out, int out_size) {
    const float* xyz   = (const float*)d_in[0];
    const float* feat  = (const float*)d_in[1];
    const float* query = (const float*)d_in[2];
    const float* fc1w  = (const float*)d_in[3];
    const float* fc1b  = (const float*)d_in[4];
    const float* fc2w  = (const float*)d_in[5];
    const float* fc2b  = (const float*)d_in[6];
    const float* d1w   = (const float*)d_in[7];
    const float* d1b   = (const float*)d_in[8];
    const float* d2w   = (const float*)d_in[9];
    const float* d2b   = (const float*)d_in[10];
    const float* g1w   = (const float*)d_in[11];
    const float* g1b   = (const float*)d_in[12];
    const float* g2w   = (const float*)d_in[13];
    const float* g2b   = (const float*)d_in[14];
    const float* wq    = (const float*)d_in[15];
    const float* wk    = (const float*)d_in[16];
    const float* wv    = (const float*)d_in[17];
    float* out = (float*)d_out;

    knn_kernel    <<<BM/8, 256>>>(xyz, query);
    qproj_kernel  <<<BM/16, 128>>>(query, wq);
    fc1kv_kernel  <<<BM, 128>>>(feat, fc1w, fc1b, wk, wv);
    pos_kernel    <<<BM, 128>>>(xyz, query, d1w, d1b, d2w, d2b);
    attnpre_kernel<<<BM, 128>>>(g1w, g1b, g2w, g2b, out);
    final_kernel  <<<BM, 256>>>(fc2w, fc2b, query, out);
}

// round 9
// speedup vs baseline: 2.9687x; 1.3376x over previous
#include <cuda_runtime.h>
#include <cuda_bf16.h>
#include <math_constants.h>
#include <cstdint>

#define Np   8192
#define DP   128
#define DM   256
#define BM   8192           // B*M queries
#define NROW 131072         // BM*16 neighbor-rows
#define RES_ELEMS (BM*DP)

// ===================== PTX helpers (baseline sm_103, no 'a' features) ======
__device__ __forceinline__ uint32_t smem_u32(const void* p) {
    uint32_t a;
    asm("{ .reg .u64 t; cvta.to.shared.u64 t, %1; cvt.u32.u64 %0, t; }" : "=r"(a) : "l"(p));
    return a;
}
__device__ __forceinline__ void cpasync16(uint32_t dst, const void* src) {
    asm volatile("cp.async.cg.shared.global [%0], [%1], 16;" :: "r"(dst), "l"(src));
}
#define CP_COMMIT() asm volatile("cp.async.commit_group;" ::: "memory")
#define CP_WAIT(n)  asm volatile("cp.async.wait_group %0;" :: "n"(n) : "memory")

__device__ __forceinline__ void ldsm4(uint32_t* r, uint32_t addr) {
    asm volatile("ldmatrix.sync.aligned.m8n8.x4.shared.b16 {%0,%1,%2,%3}, [%4];"
        : "=r"(r[0]), "=r"(r[1]), "=r"(r[2]), "=r"(r[3]) : "r"(addr));
}
__device__ __forceinline__ void mma16816(float* c, const uint32_t* a, const uint32_t* b) {
    asm volatile("mma.sync.aligned.m16n8k16.row.col.f32.bf16.bf16.f32 "
        "{%0,%1,%2,%3}, {%4,%5,%6,%7}, {%8,%9}, {%0,%1,%2,%3};"
        : "+f"(c[0]), "+f"(c[1]), "+f"(c[2]), "+f"(c[3])
        : "r"(a[0]), "r"(a[1]), "r"(a[2]), "r"(a[3]), "r"(b[0]), "r"(b[1]));
}

// ===================== scratch =====================
__device__ int   g_knn[BM*16];
__device__ float g_q  [BM*DM];
__device__ float g_v  [NROW*DM];
__device__ float g_pos[NROW*DM];
__device__ __align__(16) __nv_bfloat16 g_qfh[BM*DP],  g_qfl[BM*DP];
__device__ __align__(16) __nv_bfloat16 g_fh [NROW*DP], g_fl [NROW*DP];
__device__ __align__(16) __nv_bfloat16 g_xhi[NROW*DM], g_xlo[NROW*DM];
__device__ __align__(16) __nv_bfloat16 g_hhi[NROW*DM], g_hlo[NROW*DM];
__device__ __align__(16) __nv_bfloat16 g_ahi[NROW*DM], g_alo[NROW*DM];
__device__ __align__(16) __nv_bfloat16 g_thi[NROW*DM], g_tlo[NROW*DM];
// transposed+split weights [N=256][K]
__device__ __align__(16) __nv_bfloat16 w_qh[DM*DP],  w_ql[DM*DP];
__device__ __align__(16) __nv_bfloat16 w_f1h[DM*DP], w_f1l[DM*DP];
__device__ __align__(16) __nv_bfloat16 w_kh[DM*DM],  w_kl[DM*DM];
__device__ __align__(16) __nv_bfloat16 w_vh[DM*DM],  w_vl[DM*DM];
__device__ __align__(16) __nv_bfloat16 w_d2h[DM*DM], w_d2l[DM*DM];
__device__ __align__(16) __nv_bfloat16 w_g1h[DM*DM], w_g1l[DM*DM];
__device__ __align__(16) __nv_bfloat16 w_g2h[DM*DM], w_g2l[DM*DM];

// ===================== KNN =====================
__global__ void knn_kernel(const float* __restrict__ xyz,
                           const float* __restrict__ query) {
    int wip  = threadIdx.x >> 5;
    int lane = threadIdx.x & 31;
    int qi   = blockIdx.x * 8 + wip;
    int b    = qi >> 11;
    const float* qp = query + (size_t)qi * 131;
    float qx = qp[0], qy = qp[1], qz = qp[2];
    float q2 = qx*qx + qy*qy + qz*qz;
    const float* xb = xyz + (size_t)b * Np * 3;

    float bd[16]; int bi[16];
#pragma unroll
    for (int i = 0; i < 16; i++) { bd[i] = CUDART_INF_F; bi[i] = 0x7fffffff; }
    float cm = CUDART_INF_F; int cmp_ = 0;

    for (int n = lane; n < Np; n += 32) {
        float x = xb[3*n], y = xb[3*n+1], z = xb[3*n+2];
        float d = q2 + (x*x + y*y + z*z) - 2.0f*(qx*x + qy*y + qz*z);
        if (d < cm) {
#pragma unroll
            for (int i = 0; i < 16; i++) if (i == cmp_) { bd[i] = d; bi[i] = n; }
            cm = -CUDART_INF_F;
#pragma unroll
            for (int i = 0; i < 16; i++) if (bd[i] > cm) { cm = bd[i]; cmp_ = i; }
        }
    }
    for (int r = 0; r < 16; r++) {
        float md = CUDART_INF_F; int mi = 0x7fffffff;
#pragma unroll
        for (int i = 0; i < 16; i++) {
            float d = bd[i]; int id = bi[i];
            if (d < md || (d == md && id < mi)) { md = d; mi = id; }
        }
#pragma unroll
        for (int off = 16; off > 0; off >>= 1) {
            float od = __shfl_down_sync(0xffffffffu, md, off);
            int   oi = __shfl_down_sync(0xffffffffu, mi, off);
            if (od < md || (od == md && oi < mi)) { md = od; mi = oi; }
        }
        int w = __shfl_sync(0xffffffffu, mi, 0);
        if (lane == 0) g_knn[qi*16 + r] = w;
#pragma unroll
        for (int i = 0; i < 16; i++) if (bi[i] == w) bd[i] = CUDART_INF_F;
    }
}

// ===================== prep kernels =====================
__global__ void wprep_kernel(const float* __restrict__ W,
                             __nv_bfloat16* __restrict__ Th,
                             __nv_bfloat16* __restrict__ Tl, int K) {
    int i = blockIdx.x * 256 + threadIdx.x;
    if (i >= K * DM) return;
    int k = i / DM, n = i % DM;
    float v = W[i];
    __nv_bfloat16 h = __float2bfloat16(v);
    Th[n*K + k] = h;
    Tl[n*K + k] = __float2bfloat16(v - __bfloat162float(h));
}

__global__ void qsplit_kernel(const float* __restrict__ query,
                              __nv_bfloat16* __restrict__ qh,
                              __nv_bfloat16* __restrict__ ql) {
    int i = blockIdx.x * 256 + threadIdx.x;   // over BM*128
    int r = i >> 7, c = i & 127;
    float v = query[(size_t)r*131 + 3 + c];
    __nv_bfloat16 h = __float2bfloat16(v);
    qh[i] = h;
    ql[i] = __float2bfloat16(v - __bfloat162float(h));
}

__global__ __launch_bounds__(128) void fgather_kernel(const float* __restrict__ feat,
                                                      __nv_bfloat16* __restrict__ fh,
                                                      __nv_bfloat16* __restrict__ fl) {
    int row = blockIdx.x;                     // 0..NROW-1
    int bm = row >> 4, b = bm >> 11;
    int idx = g_knn[bm*16 + (row & 15)];
    float v = feat[((size_t)b*Np + idx)*DP + threadIdx.x];
    __nv_bfloat16 h = __float2bfloat16(v);
    size_t o = (size_t)row*DP + threadIdx.x;
    fh[o] = h;
    fl[o] = __float2bfloat16(v - __bfloat162float(h));
}

__global__ __launch_bounds__(256) void hprep_kernel(const float* __restrict__ xyz,
                                                    const float* __restrict__ query,
                                                    const float* __restrict__ d1w,
                                                    const float* __restrict__ d1b) {
    __shared__ float sdel[16][4];
    int bm = blockIdx.x, b = bm >> 11, tid = threadIdx.x;
    if (tid < 16) {
        int idx = g_knn[bm*16 + tid];
        const float* qp = query + (size_t)bm*131;
        const float* xp = xyz + ((size_t)b*Np + idx)*3;
        sdel[tid][0] = qp[0] - xp[0];
        sdel[tid][1] = qp[1] - xp[1];
        sdel[tid][2] = qp[2] - xp[2];
    }
    __syncthreads();
    int c = tid;
    float w0 = d1w[c], w1 = d1w[DM + c], w2 = d1w[2*DM + c], bb = d1b[c];
#pragma unroll
    for (int r = 0; r < 16; r++) {
        float v = fmaxf(fmaf(sdel[r][2], w2, fmaf(sdel[r][1], w1, fmaf(sdel[r][0], w0, bb))), 0.f);
        size_t o = (size_t)(bm*16 + r)*DM + c;
        __nv_bfloat16 h = __float2bfloat16(v);
        g_hhi[o] = h;
        g_hlo[o] = __float2bfloat16(v - __bfloat162float(h));
    }
}

// ===================== mma.sync split-bf16 GEMM =====================
// C(tile 128 x 256) = A(128 x K) @ B[256][K]^T (+bias), 3-term bf16 split, f32 acc
// epi: 0 = fp32 -> outf; 1 = split; 2 = relu+split; 3 = (q - d + pos) split
#define AH_OFF 0
#define AL_OFF 18432
#define BH_OFF 36864
#define BL_OFF 73728
#define STG    110592
#define SMEM_TOTAL (2*STG)

__device__ __forceinline__ void load_chunk(uint32_t sbase,
    const __nv_bfloat16* Ah, const __nv_bfloat16* Al,
    const __nv_bfloat16* Bh, const __nv_bfloat16* Bl,
    int tile, int Kdim, int kc0, int tid)
{
#pragma unroll
    for (int g = 0; g < 2; g++) {
        int e = g*512 + tid;
        int r = e >> 3, c = e & 7;
        size_t off = (size_t)(tile*128 + r)*Kdim + kc0 + c*8;
        cpasync16(sbase + AH_OFF + r*144 + c*16, Ah + off);
        cpasync16(sbase + AL_OFF + r*144 + c*16, Al + off);
    }
#pragma unroll
    for (int g = 0; g < 4; g++) {
        int e = g*512 + tid;
        int n = e >> 3, c = e & 7;
        size_t off = (size_t)n*Kdim + kc0 + c*8;
        cpasync16(sbase + BH_OFF + n*144 + c*16, Bh + off);
        cpasync16(sbase + BL_OFF + n*144 + c*16, Bl + off);
    }
}

__global__ __launch_bounds__(512, 1) void tc_gemm(
    const __nv_bfloat16* __restrict__ Ahi, const __nv_bfloat16* __restrict__ Alo,
    const __nv_bfloat16* __restrict__ Bhi, const __nv_bfloat16* __restrict__ Blo,
    const float* __restrict__ bias,
    const float* __restrict__ qv, const float* __restrict__ pos,
    float* __restrict__ outf,
    __nv_bfloat16* __restrict__ outh, __nv_bfloat16* __restrict__ outl,
    int Kdim, int epi_mode)
{
    extern __shared__ char dsm[];
    uint32_t sb = smem_u32(dsm);
    int tid = threadIdx.x, lid = tid & 31, wid = tid >> 5;
    int tile = blockIdx.x;
    int mw = wid & 3, nw = wid >> 2;
    int mbase = mw*32, nbase = nw*64;

    uint32_t aRow  = mbase + (lid & 15);
    uint32_t aKoff = ((lid >> 4) & 1) * 16;
    uint32_t bRow  = (lid & 7) + ((lid >> 4) & 1) * 8;
    uint32_t bKoff = ((lid >> 3) & 1) * 16;

    float acc[2][8][4];
#pragma unroll
    for (int i = 0; i < 2; i++)
#pragma unroll
        for (int j = 0; j < 8; j++)
#pragma unroll
            for (int e = 0; e < 4; e++) acc[i][j][e] = 0.f;

    const int nst = Kdim >> 6;
    load_chunk(sb, Ahi, Alo, Bhi, Blo, tile, Kdim, 0, tid);
    CP_COMMIT();

    for (int s = 0; s < nst; s++) {
        if (s + 1 < nst) {
            load_chunk(sb + ((s+1)&1)*STG, Ahi, Alo, Bhi, Blo, tile, Kdim, (s+1)*64, tid);
            CP_COMMIT();
            CP_WAIT(1);
        } else {
            CP_WAIT(0);
        }
        __syncthreads();

        uint32_t stb = sb + (s&1)*STG;
#pragma unroll
        for (int k16 = 0; k16 < 4; k16++) {
            uint32_t ah[2][4], alr[2][4];
            uint32_t ab = stb + AH_OFF + aRow*144 + k16*32 + aKoff;
            ldsm4(ah[0], ab);
            ldsm4(ah[1], ab + 16*144);
            ldsm4(alr[0], ab + (AL_OFF - AH_OFF));
            ldsm4(alr[1], ab + (AL_OFF - AH_OFF) + 16*144);
#pragma unroll
            for (int np = 0; np < 4; np++) {
                uint32_t bh[4], bl[4];
                uint32_t bb = stb + BH_OFF + (nbase + np*16 + bRow)*144 + k16*32 + bKoff;
                ldsm4(bh, bb);
                ldsm4(bl, bb + (BL_OFF - BH_OFF));
#pragma unroll
                for (int mf = 0; mf < 2; mf++) {
                    mma16816(acc[mf][2*np],   ah[mf],  bh);
                    mma16816(acc[mf][2*np],   alr[mf], bh);
                    mma16816(acc[mf][2*np],   ah[mf],  bl);
                    mma16816(acc[mf][2*np+1], ah[mf],  bh + 2);
                    mma16816(acc[mf][2*np+1], alr[mf], bh + 2);
                    mma16816(acc[mf][2*np+1], ah[mf],  bl + 2);
                }
            }
        }
        __syncthreads();
    }

    // ---- epilogue: acc -> smem stage -> coalesced gmem
    float* eb = (float*)dsm;   // [128][264]
#pragma unroll
    for (int mf = 0; mf < 2; mf++)
#pragma unroll
        for (int nf = 0; nf < 8; nf++) {
            int m = mbase + mf*16 + (lid >> 2);
            int n = nbase + nf*8 + (lid & 3)*2;
            eb[m*264 + n]     = acc[mf][nf][0];
            eb[m*264 + n + 1] = acc[mf][nf][1];
            eb[(m+8)*264 + n]     = acc[mf][nf][2];
            eb[(m+8)*264 + n + 1] = acc[mf][nf][3];
        }
    __syncthreads();

    for (int i = tid; i < 128*256; i += 512) {
        int row = i >> 8, col = i & 255;
        float v = eb[row*264 + col];
        if (bias) v += bias[col];
        size_t o = (size_t)(tile*128 + row) * DM + col;
        if (epi_mode == 0) {
            outf[o] = v;
        } else if (epi_mode == 1) {
            __nv_bfloat16 h = __float2bfloat16(v);
            outh[o] = h; outl[o] = __float2bfloat16(v - __bfloat162float(h));
        } else if (epi_mode == 2) {
            v = fmaxf(v, 0.f);
            __nv_bfloat16 h = __float2bfloat16(v);
            outh[o] = h; outl[o] = __float2bfloat16(v - __bfloat162float(h));
        } else {
            int bm = (tile*128 + row) >> 4;
            v = qv[(size_t)bm*DM + col] - v + pos[o];
            __nv_bfloat16 h = __float2bfloat16(v);
            outh[o] = h; outl[o] = __float2bfloat16(v - __bfloat162float(h));
        }
    }
}

// ===================== softmax + weighted sum + fc2 + residual ==============
__global__ void final_kernel(const float* __restrict__ fc2w, const float* __restrict__ fc2b,
                             const float* __restrict__ query, float* __restrict__ out) {
    __shared__ float sres[DM];
    int bm = blockIdx.x, c = threadIdx.x;
    float* attn = out + RES_ELEMS + (size_t)bm*16*DM;
    float ap[16];
#pragma unroll
    for (int j = 0; j < 16; j++) ap[j] = attn[j*DM + c] * 0.0625f;
    float mx = ap[0];
#pragma unroll
    for (int j = 1; j < 16; j++) mx = fmaxf(mx, ap[j]);
    float s = 0.f;
#pragma unroll
    for (int j = 0; j < 16; j++) { ap[j] = expf(ap[j] - mx); s += ap[j]; }
    float inv = 1.0f / s;
    const float* vr = g_v   + (size_t)bm*16*DM;
    const float* pr = g_pos + (size_t)bm*16*DM;
    float resc = 0.f;
#pragma unroll
    for (int j = 0; j < 16; j++) {
        float a = ap[j] * inv;
        attn[j*DM + c] = a;
        resc = fmaf(a, vr[j*DM + c] + pr[j*DM + c], resc);
    }
    sres[c] = resc;
    __syncthreads();
    if (c < DP) {
        float acc = fc2b[c];
#pragma unroll 4
        for (int k = 0; k < DM; k++) acc = fmaf(sres[k], fc2w[k*DP + c], acc);
        acc += query[(size_t)bm*131 + 3 + c];
        out[(size_t)bm*DP + c] = acc;
    }
}

// ===================== launch =====================
extern "C" void kernel_launch(void* const* d_in, const int* in_sizes, int n_in,
                              void* d_out, int out_size) {
    const float* xyz   = (const float*)d_in[0];
    const float* feat  = (const float*)d_in[1];
    const float* query = (const float*)d_in[2];
    const float* fc1w  = (const float*)d_in[3];
    const float* fc1b  = (const float*)d_in[4];
    const float* fc2w  = (const float*)d_in[5];
    const float* fc2b  = (const float*)d_in[6];
    const float* d1w   = (const float*)d_in[7];
    const float* d1b   = (const float*)d_in[8];
    const float* d2w   = (const float*)d_in[9];
    const float* d2b   = (const float*)d_in[10];
    const float* g1w   = (const float*)d_in[11];
    const float* g1b   = (const float*)d_in[12];
    const float* g2w   = (const float*)d_in[13];
    const float* g2b   = (const float*)d_in[14];
    const float* wq    = (const float*)d_in[15];
    const float* wk    = (const float*)d_in[16];
    const float* wv    = (const float*)d_in[17];
    float* out = (float*)d_out;

    static int smem_set = 0;
    if (!smem_set) {
        cudaFuncSetAttribute(tc_gemm, cudaFuncAttributeMaxDynamicSharedMemorySize, SMEM_TOTAL);
        smem_set = 1;
    }

    __nv_bfloat16 *p_qh, *p_ql, *p_f1h, *p_f1l, *p_kh, *p_kl, *p_vh, *p_vl,
                  *p_d2h, *p_d2l, *p_g1h, *p_g1l, *p_g2h, *p_g2l;
    cudaGetSymbolAddress((void**)&p_qh,  w_qh);  cudaGetSymbolAddress((void**)&p_ql,  w_ql);
    cudaGetSymbolAddress((void**)&p_f1h, w_f1h); cudaGetSymbolAddress((void**)&p_f1l, w_f1l);
    cudaGetSymbolAddress((void**)&p_kh,  w_kh);  cudaGetSymbolAddress((void**)&p_kl,  w_kl);
    cudaGetSymbolAddress((void**)&p_vh,  w_vh);  cudaGetSymbolAddress((void**)&p_vl,  w_vl);
    cudaGetSymbolAddress((void**)&p_d2h, w_d2h); cudaGetSymbolAddress((void**)&p_d2l, w_d2l);
    cudaGetSymbolAddress((void**)&p_g1h, w_g1h); cudaGetSymbolAddress((void**)&p_g1l, w_g1l);
    cudaGetSymbolAddress((void**)&p_g2h, w_g2h); cudaGetSymbolAddress((void**)&p_g2l, w_g2l);
    float *p_q, *p_v, *p_pos;
    __nv_bfloat16 *p_qfh, *p_qfl, *p_fh, *p_fl, *p_xh, *p_xl, *p_hh, *p_hl,
                  *p_ah, *p_al, *p_th, *p_tl;
    cudaGetSymbolAddress((void**)&p_q,   g_q);
    cudaGetSymbolAddress((void**)&p_v,   g_v);
    cudaGetSymbolAddress((void**)&p_pos, g_pos);
    cudaGetSymbolAddress((void**)&p_qfh, g_qfh); cudaGetSymbolAddress((void**)&p_qfl, g_qfl);
    cudaGetSymbolAddress((void**)&p_fh,  g_fh);  cudaGetSymbolAddress((void**)&p_fl,  g_fl);
    cudaGetSymbolAddress((void**)&p_xh,  g_xhi); cudaGetSymbolAddress((void**)&p_xl,  g_xlo);
    cudaGetSymbolAddress((void**)&p_hh,  g_hhi); cudaGetSymbolAddress((void**)&p_hl,  g_hlo);
    cudaGetSymbolAddress((void**)&p_ah,  g_ahi); cudaGetSymbolAddress((void**)&p_al,  g_alo);
    cudaGetSymbolAddress((void**)&p_th,  g_thi); cudaGetSymbolAddress((void**)&p_tl,  g_tlo);

    knn_kernel<<<BM/8, 256>>>(xyz, query);

    wprep_kernel<<<DP, 256>>>(wq,   p_qh,  p_ql,  DP);
    wprep_kernel<<<DP, 256>>>(fc1w, p_f1h, p_f1l, DP);
    wprep_kernel<<<DM, 256>>>(wk,   p_kh,  p_kl,  DM);
    wprep_kernel<<<DM, 256>>>(wv,   p_vh,  p_vl,  DM);
    wprep_kernel<<<DM, 256>>>(d2w,  p_d2h, p_d2l, DM);
    wprep_kernel<<<DM, 256>>>(g1w,  p_g1h, p_g1l, DM);
    wprep_kernel<<<DM, 256>>>(g2w,  p_g2h, p_g2l, DM);

    qsplit_kernel <<<BM*DP/256, 256>>>(query, p_qfh, p_qfl);
    fgather_kernel<<<NROW, 128>>>(feat, p_fh, p_fl);
    hprep_kernel  <<<BM, 256>>>(xyz, query, d1w, d1b);

    // q = query_f @ wq                        (fp32 -> g_q)
    tc_gemm<<<BM/128, 512, SMEM_TOTAL>>>(p_qfh, p_qfl, p_qh, p_ql,
        nullptr, nullptr, nullptr, p_q, nullptr, nullptr, DP, 0);
    // x = gathered_feat @ fc1 + b             (split -> g_x)
    tc_gemm<<<NROW/128, 512, SMEM_TOTAL>>>(p_fh, p_fl, p_f1h, p_f1l,
        fc1b, nullptr, nullptr, nullptr, p_xh, p_xl, DP, 1);
    // pos = h @ d2 + b                        (fp32 -> g_pos)
    tc_gemm<<<NROW/128, 512, SMEM_TOTAL>>>(p_hh, p_hl, p_d2h, p_d2l,
        d2b, nullptr, nullptr, p_pos, nullptr, nullptr, DM, 0);
    // v = x @ wv                              (fp32 -> g_v)
    tc_gemm<<<NROW/128, 512, SMEM_TOTAL>>>(p_xh, p_xl, p_vh, p_vl,
        nullptr, nullptr, nullptr, p_v, nullptr, nullptr, DM, 0);
    // a = q - x@wk + pos                      (split -> g_a)
    tc_gemm<<<NROW/128, 512, SMEM_TOTAL>>>(p_xh, p_xl, p_kh, p_kl,
        nullptr, p_q, p_pos, nullptr, p_ah, p_al, DM, 3);
    // t = relu(a @ g1 + b)                    (split -> g_t)
    tc_gemm<<<NROW/128, 512, SMEM_TOTAL>>>(p_ah, p_al, p_g1h, p_g1l,
        g1b, nullptr, nullptr, nullptr, p_th, p_tl, DM, 2);
    // attn_pre = t @ g2 + b -> out attn region
    tc_gemm<<<NROW/128, 512, SMEM_TOTAL>>>(p_th, p_tl, p_g2h, p_g2l,
        g2b, nullptr, nullptr, out + RES_ELEMS, nullptr, nullptr, DM, 0);

    final_kernel<<<BM, 256>>>(fc2w, fc2b, query, out);
}

// round 10
// speedup vs baseline: 3.6830x; 1.2406x over previous
#include <cuda_runtime.h>
#include <cuda_bf16.h>
#include <math_constants.h>
#include <cstdint>

#define Np   8192
#define DP   128
#define DM   256
#define BM   8192           // B*M queries
#define NPT  32768          // B*Np distinct points
#define NROW 131072         // BM*16 (query,neighbor) rows
#define RES_ELEMS (BM*DP)

// ===================== PTX helpers (baseline sm_103) =====================
__device__ __forceinline__ uint32_t smem_u32(const void* p) {
    uint32_t a;
    asm("{ .reg .u64 t; cvta.to.shared.u64 t, %1; cvt.u32.u64 %0, t; }" : "=r"(a) : "l"(p));
    return a;
}
__device__ __forceinline__ void cpasync16(uint32_t dst, const void* src) {
    asm volatile("cp.async.cg.shared.global [%0], [%1], 16;" :: "r"(dst), "l"(src));
}
#define CP_COMMIT() asm volatile("cp.async.commit_group;" ::: "memory")
#define CP_WAIT(n)  asm volatile("cp.async.wait_group %0;" :: "n"(n) : "memory")

__device__ __forceinline__ void ldsm4(uint32_t* r, uint32_t addr) {
    asm volatile("ldmatrix.sync.aligned.m8n8.x4.shared.b16 {%0,%1,%2,%3}, [%4];"
        : "=r"(r[0]), "=r"(r[1]), "=r"(r[2]), "=r"(r[3]) : "r"(addr));
}
__device__ __forceinline__ void mma16816(float* c, const uint32_t* a, const uint32_t* b) {
    asm volatile("mma.sync.aligned.m16n8k16.row.col.f32.bf16.bf16.f32 "
        "{%0,%1,%2,%3}, {%4,%5,%6,%7}, {%8,%9}, {%0,%1,%2,%3};"
        : "+f"(c[0]), "+f"(c[1]), "+f"(c[2]), "+f"(c[3])
        : "r"(a[0]), "r"(a[1]), "r"(a[2]), "r"(a[3]), "r"(b[0]), "r"(b[1]));
}

// ===================== scratch =====================
__device__ int   g_knn[BM*16];
__device__ float g_q  [BM*DM];
__device__ float g_kpt[NPT*DM];
__device__ float g_vpt[NPT*DM];
__device__ float g_pos[NROW*DM];
__device__ __align__(16) __nv_bfloat16 g_qfh[BM*DP],  g_qfl[BM*DP];
__device__ __align__(16) __nv_bfloat16 g_fsh[NPT*DP], g_fsl[NPT*DP];
__device__ __align__(16) __nv_bfloat16 g_xph[NPT*DM], g_xpl[NPT*DM];
__device__ __align__(16) __nv_bfloat16 g_hhi[NROW*DM], g_hlo[NROW*DM];
__device__ __align__(16) __nv_bfloat16 g_ahi[NROW*DM], g_alo[NROW*DM];
__device__ __align__(16) __nv_bfloat16 g_thi[NROW*DM], g_tlo[NROW*DM];
// transposed+split weights [N=256][K]
__device__ __align__(16) __nv_bfloat16 w_qh[DM*DP],  w_ql[DM*DP];
__device__ __align__(16) __nv_bfloat16 w_f1h[DM*DP], w_f1l[DM*DP];
__device__ __align__(16) __nv_bfloat16 w_kh[DM*DM],  w_kl[DM*DM];
__device__ __align__(16) __nv_bfloat16 w_vh[DM*DM],  w_vl[DM*DM];
__device__ __align__(16) __nv_bfloat16 w_d2h[DM*DM], w_d2l[DM*DM];
__device__ __align__(16) __nv_bfloat16 w_g1h[DM*DM], w_g1l[DM*DM];
__device__ __align__(16) __nv_bfloat16 w_g2h[DM*DM], w_g2l[DM*DM];

// ===================== KNN =====================
__global__ void knn_kernel(const float* __restrict__ xyz,
                           const float* __restrict__ query) {
    int wip  = threadIdx.x >> 5;
    int lane = threadIdx.x & 31;
    int qi   = blockIdx.x * 8 + wip;
    int b    = qi >> 11;
    const float* qp = query + (size_t)qi * 131;
    float qx = qp[0], qy = qp[1], qz = qp[2];
    float q2 = qx*qx + qy*qy + qz*qz;
    const float* xb = xyz + (size_t)b * Np * 3;

    float bd[16]; int bi[16];
#pragma unroll
    for (int i = 0; i < 16; i++) { bd[i] = CUDART_INF_F; bi[i] = 0x7fffffff; }
    float cm = CUDART_INF_F; int cmp_ = 0;

    for (int n = lane; n < Np; n += 32) {
        float x = xb[3*n], y = xb[3*n+1], z = xb[3*n+2];
        float d = q2 + (x*x + y*y + z*z) - 2.0f*(qx*x + qy*y + qz*z);
        if (d < cm) {
#pragma unroll
            for (int i = 0; i < 16; i++) if (i == cmp_) { bd[i] = d; bi[i] = n; }
            cm = -CUDART_INF_F;
#pragma unroll
            for (int i = 0; i < 16; i++) if (bd[i] > cm) { cm = bd[i]; cmp_ = i; }
        }
    }
    for (int r = 0; r < 16; r++) {
        float md = CUDART_INF_F; int mi = 0x7fffffff;
#pragma unroll
        for (int i = 0; i < 16; i++) {
            float d = bd[i]; int id = bi[i];
            if (d < md || (d == md && id < mi)) { md = d; mi = id; }
        }
#pragma unroll
        for (int off = 16; off > 0; off >>= 1) {
            float od = __shfl_down_sync(0xffffffffu, md, off);
            int   oi = __shfl_down_sync(0xffffffffu, mi, off);
            if (od < md || (od == md && oi < mi)) { md = od; mi = oi; }
        }
        int w = __shfl_sync(0xffffffffu, mi, 0);
        if (lane == 0) g_knn[qi*16 + r] = w;
#pragma unroll
        for (int i = 0; i < 16; i++) if (bi[i] == w) bd[i] = CUDART_INF_F;
    }
}

// ===================== prep kernels =====================
__global__ void wprep_kernel(const float* __restrict__ W,
                             __nv_bfloat16* __restrict__ Th,
                             __nv_bfloat16* __restrict__ Tl, int K) {
    int i = blockIdx.x * 256 + threadIdx.x;
    if (i >= K * DM) return;
    int k = i / DM, n = i % DM;
    float v = W[i];
    __nv_bfloat16 h = __float2bfloat16(v);
    Th[n*K + k] = h;
    Tl[n*K + k] = __float2bfloat16(v - __bfloat162float(h));
}

__global__ void qsplit_kernel(const float* __restrict__ query,
                              __nv_bfloat16* __restrict__ qh,
                              __nv_bfloat16* __restrict__ ql) {
    int i = blockIdx.x * 256 + threadIdx.x;   // over BM*128
    int r = i >> 7, c = i & 127;
    float v = query[(size_t)r*131 + 3 + c];
    __nv_bfloat16 h = __float2bfloat16(v);
    qh[i] = h;
    ql[i] = __float2bfloat16(v - __bfloat162float(h));
}

__global__ void fsplit_kernel(const float* __restrict__ feat,
                              __nv_bfloat16* __restrict__ fh,
                              __nv_bfloat16* __restrict__ fl) {
    int i = blockIdx.x * 256 + threadIdx.x;   // over NPT*128
    float v = feat[i];
    __nv_bfloat16 h = __float2bfloat16(v);
    fh[i] = h;
    fl[i] = __float2bfloat16(v - __bfloat162float(h));
}

__global__ __launch_bounds__(256) void hprep_kernel(const float* __restrict__ xyz,
                                                    const float* __restrict__ query,
                                                    const float* __restrict__ d1w,
                                                    const float* __restrict__ d1b) {
    __shared__ float sdel[16][4];
    int bm = blockIdx.x, b = bm >> 11, tid = threadIdx.x;
    if (tid < 16) {
        int idx = g_knn[bm*16 + tid];
        const float* qp = query + (size_t)bm*131;
        const float* xp = xyz + ((size_t)b*Np + idx)*3;
        sdel[tid][0] = qp[0] - xp[0];
        sdel[tid][1] = qp[1] - xp[1];
        sdel[tid][2] = qp[2] - xp[2];
    }
    __syncthreads();
    int c = tid;
    float w0 = d1w[c], w1 = d1w[DM + c], w2 = d1w[2*DM + c], bb = d1b[c];
#pragma unroll
    for (int r = 0; r < 16; r++) {
        float v = fmaxf(fmaf(sdel[r][2], w2, fmaf(sdel[r][1], w1, fmaf(sdel[r][0], w0, bb))), 0.f);
        size_t o = (size_t)(bm*16 + r)*DM + c;
        __nv_bfloat16 h = __float2bfloat16(v);
        g_hhi[o] = h;
        g_hlo[o] = __float2bfloat16(v - __bfloat162float(h));
    }
}

// ===================== mma.sync split-bf16 GEMM =====================
// C(tile 128 x 256) = A(128 x K) @ B[256][K]^T (+bias), 3-term bf16 split, f32 acc
// epi: 0 = fp32 -> outf
//      1 = split -> outh/outl
//      2 = relu+split -> outh/outl
//      3 = pos-combined: outf=pos fp32; a = q[bm] - kpt[gather] + pos -> split
#define AH_OFF 0
#define AL_OFF 18432
#define BH_OFF 36864
#define BL_OFF 73728
#define STG    110592
#define SMEM_TOTAL (2*STG)

__device__ __forceinline__ void load_chunk(uint32_t sbase,
    const __nv_bfloat16* Ah, const __nv_bfloat16* Al,
    const __nv_bfloat16* Bh, const __nv_bfloat16* Bl,
    int tile, int Kdim, int kc0, int tid)
{
#pragma unroll
    for (int g = 0; g < 2; g++) {
        int e = g*512 + tid;
        int r = e >> 3, c = e & 7;
        size_t off = (size_t)(tile*128 + r)*Kdim + kc0 + c*8;
        cpasync16(sbase + AH_OFF + r*144 + c*16, Ah + off);
        cpasync16(sbase + AL_OFF + r*144 + c*16, Al + off);
    }
#pragma unroll
    for (int g = 0; g < 4; g++) {
        int e = g*512 + tid;
        int n = e >> 3, c = e & 7;
        size_t off = (size_t)n*Kdim + kc0 + c*8;
        cpasync16(sbase + BH_OFF + n*144 + c*16, Bh + off);
        cpasync16(sbase + BL_OFF + n*144 + c*16, Bl + off);
    }
}

__global__ __launch_bounds__(512, 1) void tc_gemm(
    const __nv_bfloat16* __restrict__ Ahi, const __nv_bfloat16* __restrict__ Alo,
    const __nv_bfloat16* __restrict__ Bhi, const __nv_bfloat16* __restrict__ Blo,
    const float* __restrict__ bias,
    const float* __restrict__ qv, const float* __restrict__ kpt,
    float* __restrict__ outf,
    __nv_bfloat16* __restrict__ outh, __nv_bfloat16* __restrict__ outl,
    int Kdim, int epi_mode)
{
    extern __shared__ char dsm[];
    uint32_t sb = smem_u32(dsm);
    int tid = threadIdx.x, lid = tid & 31, wid = tid >> 5;
    int tile = blockIdx.x;
    int mw = wid & 3, nw = wid >> 2;
    int mbase = mw*32, nbase = nw*64;

    uint32_t aRow  = mbase + (lid & 15);
    uint32_t aKoff = ((lid >> 4) & 1) * 16;
    uint32_t bRow  = (lid & 7) + ((lid >> 4) & 1) * 8;
    uint32_t bKoff = ((lid >> 3) & 1) * 16;

    float acc[2][8][4];
#pragma unroll
    for (int i = 0; i < 2; i++)
#pragma unroll
        for (int j = 0; j < 8; j++)
#pragma unroll
            for (int e = 0; e < 4; e++) acc[i][j][e] = 0.f;

    const int nst = Kdim >> 6;
    load_chunk(sb, Ahi, Alo, Bhi, Blo, tile, Kdim, 0, tid);
    CP_COMMIT();

    for (int s = 0; s < nst; s++) {
        if (s + 1 < nst) {
            load_chunk(sb + ((s+1)&1)*STG, Ahi, Alo, Bhi, Blo, tile, Kdim, (s+1)*64, tid);
            CP_COMMIT();
            CP_WAIT(1);
        } else {
            CP_WAIT(0);
        }
        __syncthreads();

        uint32_t stb = sb + (s&1)*STG;
#pragma unroll
        for (int k16 = 0; k16 < 4; k16++) {
            uint32_t ah[2][4], alr[2][4];
            uint32_t ab = stb + AH_OFF + aRow*144 + k16*32 + aKoff;
            ldsm4(ah[0], ab);
            ldsm4(ah[1], ab + 16*144);
            ldsm4(alr[0], ab + (AL_OFF - AH_OFF));
            ldsm4(alr[1], ab + (AL_OFF - AH_OFF) + 16*144);
#pragma unroll
            for (int np = 0; np < 4; np++) {
                uint32_t bh[4], bl[4];
                uint32_t bb = stb + BH_OFF + (nbase + np*16 + bRow)*144 + k16*32 + bKoff;
                ldsm4(bh, bb);
                ldsm4(bl, bb + (BL_OFF - BH_OFF));
#pragma unroll
                for (int mf = 0; mf < 2; mf++) {
                    mma16816(acc[mf][2*np],   ah[mf],  bh);
                    mma16816(acc[mf][2*np],   alr[mf], bh);
                    mma16816(acc[mf][2*np],   ah[mf],  bl);
                    mma16816(acc[mf][2*np+1], ah[mf],  bh + 2);
                    mma16816(acc[mf][2*np+1], alr[mf], bh + 2);
                    mma16816(acc[mf][2*np+1], ah[mf],  bl + 2);
                }
            }
        }
        __syncthreads();
    }

    // ---- epilogue: acc -> smem stage -> coalesced gmem
    float* eb = (float*)dsm;   // [128][264]
#pragma unroll
    for (int mf = 0; mf < 2; mf++)
#pragma unroll
        for (int nf = 0; nf < 8; nf++) {
            int m = mbase + mf*16 + (lid >> 2);
            int n = nbase + nf*8 + (lid & 3)*2;
            eb[m*264 + n]     = acc[mf][nf][0];
            eb[m*264 + n + 1] = acc[mf][nf][1];
            eb[(m+8)*264 + n]     = acc[mf][nf][2];
            eb[(m+8)*264 + n + 1] = acc[mf][nf][3];
        }
    __syncthreads();

    for (int i = tid; i < 128*256; i += 512) {
        int row = i >> 8, col = i & 255;
        float v = eb[row*264 + col];
        if (bias) v += bias[col];
        size_t o = (size_t)(tile*128 + row) * DM + col;
        if (epi_mode == 0) {
            outf[o] = v;
        } else if (epi_mode == 1) {
            __nv_bfloat16 h = __float2bfloat16(v);
            outh[o] = h; outl[o] = __float2bfloat16(v - __bfloat162float(h));
        } else if (epi_mode == 2) {
            v = fmaxf(v, 0.f);
            __nv_bfloat16 h = __float2bfloat16(v);
            outh[o] = h; outl[o] = __float2bfloat16(v - __bfloat162float(h));
        } else {  // pos-combined
            outf[o] = v;                           // g_pos
            int row_g = tile*128 + row;
            int bm = row_g >> 4, j = row_g & 15, b = bm >> 11;
            int idx = g_knn[bm*16 + j];
            float a = qv[(size_t)bm*DM + col]
                    - kpt[((size_t)b*Np + idx)*DM + col] + v;
            __nv_bfloat16 h = __float2bfloat16(a);
            outh[o] = h; outl[o] = __float2bfloat16(a - __bfloat162float(h));
        }
    }
}

// ===================== softmax + weighted sum + fc2 + residual ==============
__global__ void final_kernel(const float* __restrict__ fc2w, const float* __restrict__ fc2b,
                             const float* __restrict__ query, float* __restrict__ out) {
    __shared__ float sres[DM];
    __shared__ int   sidx[16];
    int bm = blockIdx.x, c = threadIdx.x, b = bm >> 11;
    if (c < 16) sidx[c] = g_knn[bm*16 + c];
    __syncthreads();
    float* attn = out + RES_ELEMS + (size_t)bm*16*DM;
    float ap[16];
#pragma unroll
    for (int j = 0; j < 16; j++) ap[j] = attn[j*DM + c] * 0.0625f;
    float mx = ap[0];
#pragma unroll
    for (int j = 1; j < 16; j++) mx = fmaxf(mx, ap[j]);
    float s = 0.f;
#pragma unroll
    for (int j = 0; j < 16; j++) { ap[j] = expf(ap[j] - mx); s += ap[j]; }
    float inv = 1.0f / s;
    const float* pr = g_pos + (size_t)bm*16*DM;
    float resc = 0.f;
#pragma unroll
    for (int j = 0; j < 16; j++) {
        float a = ap[j] * inv;
        attn[j*DM + c] = a;
        float vv = g_vpt[((size_t)b*Np + sidx[j])*DM + c];
        resc = fmaf(a, vv + pr[j*DM + c], resc);
    }
    sres[c] = resc;
    __syncthreads();
    if (c < DP) {
        float acc = fc2b[c];
#pragma unroll 4
        for (int k = 0; k < DM; k++) acc = fmaf(sres[k], fc2w[k*DP + c], acc);
        acc += query[(size_t)bm*131 + 3 + c];
        out[(size_t)bm*DP + c] = acc;
    }
}

// ===================== launch =====================
extern "C" void kernel_launch(void* const* d_in, const int* in_sizes, int n_in,
                              void* d_out, int out_size) {
    const float* xyz   = (const float*)d_in[0];
    const float* feat  = (const float*)d_in[1];
    const float* query = (const float*)d_in[2];
    const float* fc1w  = (const float*)d_in[3];
    const float* fc1b  = (const float*)d_in[4];
    const float* fc2w  = (const float*)d_in[5];
    const float* fc2b  = (const float*)d_in[6];
    const float* d1w   = (const float*)d_in[7];
    const float* d1b   = (const float*)d_in[8];
    const float* d2w   = (const float*)d_in[9];
    const float* d2b   = (const float*)d_in[10];
    const float* g1w   = (const float*)d_in[11];
    const float* g1b   = (const float*)d_in[12];
    const float* g2w   = (const float*)d_in[13];
    const float* g2b   = (const float*)d_in[14];
    const float* wq    = (const float*)d_in[15];
    const float* wk    = (const float*)d_in[16];
    const float* wv    = (const float*)d_in[17];
    float* out = (float*)d_out;

    static int smem_set = 0;
    if (!smem_set) {
        cudaFuncSetAttribute(tc_gemm, cudaFuncAttributeMaxDynamicSharedMemorySize, SMEM_TOTAL);
        smem_set = 1;
    }

    __nv_bfloat16 *p_qh, *p_ql, *p_f1h, *p_f1l, *p_kh, *p_kl, *p_vh, *p_vl,
                  *p_d2h, *p_d2l, *p_g1h, *p_g1l, *p_g2h, *p_g2l;
    cudaGetSymbolAddress((void**)&p_qh,  w_qh);  cudaGetSymbolAddress((void**)&p_ql,  w_ql);
    cudaGetSymbolAddress((void**)&p_f1h, w_f1h); cudaGetSymbolAddress((void**)&p_f1l, w_f1l);
    cudaGetSymbolAddress((void**)&p_kh,  w_kh);  cudaGetSymbolAddress((void**)&p_kl,  w_kl);
    cudaGetSymbolAddress((void**)&p_vh,  w_vh);  cudaGetSymbolAddress((void**)&p_vl,  w_vl);
    cudaGetSymbolAddress((void**)&p_d2h, w_d2h); cudaGetSymbolAddress((void**)&p_d2l, w_d2l);
    cudaGetSymbolAddress((void**)&p_g1h, w_g1h); cudaGetSymbolAddress((void**)&p_g1l, w_g1l);
    cudaGetSymbolAddress((void**)&p_g2h, w_g2h); cudaGetSymbolAddress((void**)&p_g2l, w_g2l);
    float *p_q, *p_kp, *p_vp, *p_pos;
    __nv_bfloat16 *p_qfh, *p_qfl, *p_fsh, *p_fsl, *p_xh, *p_xl, *p_hh, *p_hl,
                  *p_ah, *p_al, *p_th, *p_tl;
    cudaGetSymbolAddress((void**)&p_q,   g_q);
    cudaGetSymbolAddress((void**)&p_kp,  g_kpt);
    cudaGetSymbolAddress((void**)&p_vp,  g_vpt);
    cudaGetSymbolAddress((void**)&p_pos, g_pos);
    cudaGetSymbolAddress((void**)&p_qfh, g_qfh); cudaGetSymbolAddress((void**)&p_qfl, g_qfl);
    cudaGetSymbolAddress((void**)&p_fsh, g_fsh); cudaGetSymbolAddress((void**)&p_fsl, g_fsl);
    cudaGetSymbolAddress((void**)&p_xh,  g_xph); cudaGetSymbolAddress((void**)&p_xl,  g_xpl);
    cudaGetSymbolAddress((void**)&p_hh,  g_hhi); cudaGetSymbolAddress((void**)&p_hl,  g_hlo);
    cudaGetSymbolAddress((void**)&p_ah,  g_ahi); cudaGetSymbolAddress((void**)&p_al,  g_alo);
    cudaGetSymbolAddress((void**)&p_th,  g_thi); cudaGetSymbolAddress((void**)&p_tl,  g_tlo);

    knn_kernel<<<BM/8, 256>>>(xyz, query);

    wprep_kernel<<<DP, 256>>>(wq,   p_qh,  p_ql,  DP);
    wprep_kernel<<<DP, 256>>>(fc1w, p_f1h, p_f1l, DP);
    wprep_kernel<<<DM, 256>>>(wk,   p_kh,  p_kl,  DM);
    wprep_kernel<<<DM, 256>>>(wv,   p_vh,  p_vl,  DM);
    wprep_kernel<<<DM, 256>>>(d2w,  p_d2h, p_d2l, DM);
    wprep_kernel<<<DM, 256>>>(g1w,  p_g1h, p_g1l, DM);
    wprep_kernel<<<DM, 256>>>(g2w,  p_g2h, p_g2l, DM);

    qsplit_kernel<<<BM*DP/256, 256>>>(query, p_qfh, p_qfl);
    fsplit_kernel<<<NPT*DP/256, 256>>>(feat, p_fsh, p_fsl);
    hprep_kernel <<<BM, 256>>>(xyz, query, d1w, d1b);

    // q = query_f @ wq                     (8192 rows, fp32 -> g_q)
    tc_gemm<<<BM/128, 512, SMEM_TOTAL>>>(p_qfh, p_qfl, p_qh, p_ql,
        nullptr, nullptr, nullptr, p_q, nullptr, nullptr, DP, 0);
    // x_pt = feat @ fc1 + b                (32768 rows, split)
    tc_gemm<<<NPT/128, 512, SMEM_TOTAL>>>(p_fsh, p_fsl, p_f1h, p_f1l,
        fc1b, nullptr, nullptr, nullptr, p_xh, p_xl, DP, 1);
    // k_pt = x_pt @ wk                     (32768 rows, fp32)
    tc_gemm<<<NPT/128, 512, SMEM_TOTAL>>>(p_xh, p_xl, p_kh, p_kl,
        nullptr, nullptr, nullptr, p_kp, nullptr, nullptr, DM, 0);
    // v_pt = x_pt @ wv                     (32768 rows, fp32)
    tc_gemm<<<NPT/128, 512, SMEM_TOTAL>>>(p_xh, p_xl, p_vh, p_vl,
        nullptr, nullptr, nullptr, p_vp, nullptr, nullptr, DM, 0);
    // pos = h @ d2 + b; a = q - k[gather] + pos   (131072 rows)
    tc_gemm<<<NROW/128, 512, SMEM_TOTAL>>>(p_hh, p_hl, p_d2h, p_d2l,
        d2b, p_q, p_kp, p_pos, p_ah, p_al, DM, 3);
    // t = relu(a @ g1 + b)                 (131072 rows, relu+split)
    tc_gemm<<<NROW/128, 512, SMEM_TOTAL>>>(p_ah, p_al, p_g1h, p_g1l,
        g1b, nullptr, nullptr, nullptr, p_th, p_tl, DM, 2);
    // attn_pre = t @ g2 + b -> out attn region
    tc_gemm<<<NROW/128, 512, SMEM_TOTAL>>>(p_th, p_tl, p_g2h, p_g2l,
        g2b, nullptr, nullptr, out + RES_ELEMS, nullptr, nullptr, DM, 0);

    final_kernel<<<BM, 256>>>(fc2w, fc2b, query, out);
}